// round 3
// baseline (speedup 1.0000x reference)
#include <cuda_runtime.h>
#include <cstdint>

#define NN 64
#define SS 64
#define CC 128
#define PP 32
#define KK 1000
#define HPG 24
#define CI 384               // 3*C
#define NS 4096              // N*S
#define MR 160               // padded rows: 128 feat + 24 h + 8 zero-pad
#define EPSV 1e-5f

#define PC_OFF  0
#define WPV_OFF 2048000      // 32*64*1000
#define SEL_OFF 2310144      // + 32*64*128

// -------- device scratch (no allocations allowed) --------
__device__ float g_xT[(size_t)PP * CI * NS];     // [p][i][col], col = n*64+s  (201 MB)
__device__ float g_W[(size_t)PP * MR * CI];      // packed weights, padded     (7.9 MB)
__device__ float g_feat[(size_t)PP * CC * NS];   // [p][c][col]                (67 MB)
__device__ float g_h[(size_t)PP * HPG * NS];     // [p][o][col]                (12.6 MB)
__device__ float g_mu1[PP * HPG];
__device__ float g_rs1[PP * HPG];
__device__ float g_score[(size_t)PP * NN * SS];  // [p][n][s]
__device__ float g_ssum[PP * NN];
__device__ int   g_idx[PP * NN];
__device__ float g_wpv[(size_t)PP * NN * CC];    // [p][n][c]
__device__ float g_sc2[PP * CC];
__device__ float g_sh2[PP * CC];

// ---------------------------------------------------------
// 1) transpose t_* [n,s,c,p] -> xT[p][tau*128+c][n*64+s]
// block: (n, tau); 512 threads; c in chunks of 4
// smem tile 4c x 64s x 33p (pad) = 33.8 KB
// ---------------------------------------------------------
__global__ __launch_bounds__(512) void k_transpose(const float* __restrict__ tf,
                                                   const float* __restrict__ ts,
                                                   const float* __restrict__ tl) {
    int n = blockIdx.x, tau = blockIdx.y;
    const float* src = (tau == 0) ? tf : (tau == 1 ? ts : tl);
    __shared__ float tile[4][64][33];
    int t = threadIdx.x;
    const float* nbase = src + (size_t)n * (SS * CC * PP);
    for (int c0 = 0; c0 < CC; c0 += 4) {
        // load 4 c-planes: each 64 s x 32 p, contiguous in p
        for (int e = t; e < 4 * 64 * 32; e += 512) {
            int cl = e >> 11;
            int r  = e & 2047;
            int s = r >> 5, pp = r & 31;
            tile[cl][s][pp] = nbase[(size_t)s * (CC * PP) + (size_t)(c0 + cl) * PP + pp];
        }
        __syncthreads();
        // store: for each (cl, pp) write 64 contiguous s
        for (int e = t; e < 4 * 32 * 64; e += 512) {
            int cl = e >> 11;
            int r  = e & 2047;
            int pp = r >> 6, s = r & 63;
            int i = tau * CC + c0 + cl;
            g_xT[((size_t)pp * CI + i) * NS + n * 64 + s] = tile[cl][s][pp];
        }
        __syncthreads();
    }
}

// ---------------------------------------------------------
// 2) pack weights: rows 0..127 = wd[p], 128..151 = w1[p], 152..159 = 0
// ---------------------------------------------------------
__global__ void k_packw(const float* __restrict__ w1, const float* __restrict__ wd) {
    int p = blockIdx.x;
    for (int e = threadIdx.x; e < MR * CI; e += blockDim.x) {
        int r = e / CI, i = e - r * CI;
        float v = 0.f;
        if (r < CC)            v = wd[((size_t)p * CC + r) * CI + i];
        else if (r < CC + HPG) v = w1[((size_t)p * HPG + (r - CC)) * CI + i];
        g_W[(size_t)p * MR * CI + e] = v;
    }
}

// ---------------------------------------------------------
// 3) main GEMM: per p, C[160 x 4096] = W[160 x 384] * X[384 x 4096]
// block = (ntile, p); 256 threads (16x16); BM=160 BN=128 BK=32; TM=10 TN=8
// register-prefetch of next k-chunk hides global latency
// ---------------------------------------------------------
__global__ __launch_bounds__(256) void k_gemmA() {
    int p = blockIdx.y;
    int n0 = blockIdx.x * 128;
    __shared__ float Ws[MR * 33];         // padded stride 33
    __shared__ float4 Xs[32 * 32];        // [kk][32 x float4]
    int t = threadIdx.x;
    int tx = t & 15, ty = t >> 4;

    float acc[10][8];
#pragma unroll
    for (int j = 0; j < 10; j++)
#pragma unroll
        for (int i = 0; i < 8; i++) acc[j][i] = 0.f;

    const float* Wp = g_W + (size_t)p * MR * CI;
    const float* Xp = g_xT + (size_t)p * CI * NS;

    // per-thread load slots: W: 1280 float4 / 256 = 5; X: 1024 / 256 = 4
    float4 wbuf[5], xbuf[4];
    int wrm[5], wrk[5], xrk[4], xc4[4];
#pragma unroll
    for (int q = 0; q < 5; q++) {
        int f = t + q * 256;
        wrm[q] = f >> 3; wrk[q] = f & 7;
    }
#pragma unroll
    for (int q = 0; q < 4; q++) {
        int f = t + q * 256;
        xrk[q] = f >> 5; xc4[q] = f & 31;
    }

    // prologue: fetch k0=0
#pragma unroll
    for (int q = 0; q < 5; q++)
        wbuf[q] = *(const float4*)(Wp + (size_t)wrm[q] * CI + wrk[q] * 4);
#pragma unroll
    for (int q = 0; q < 4; q++)
        xbuf[q] = *(const float4*)(Xp + (size_t)xrk[q] * NS + n0 + xc4[q] * 4);

    for (int k0 = 0; k0 < CI; k0 += 32) {
        // commit prefetched chunk to smem
#pragma unroll
        for (int q = 0; q < 5; q++) {
            int b = wrm[q] * 33 + wrk[q] * 4;
            Ws[b] = wbuf[q].x; Ws[b + 1] = wbuf[q].y; Ws[b + 2] = wbuf[q].z; Ws[b + 3] = wbuf[q].w;
        }
#pragma unroll
        for (int q = 0; q < 4; q++)
            Xs[xrk[q] * 32 + xc4[q]] = xbuf[q];
        __syncthreads();

        // prefetch next chunk while computing
        int kn = k0 + 32;
        if (kn < CI) {
#pragma unroll
            for (int q = 0; q < 5; q++)
                wbuf[q] = *(const float4*)(Wp + (size_t)wrm[q] * CI + kn + wrk[q] * 4);
#pragma unroll
            for (int q = 0; q < 4; q++)
                xbuf[q] = *(const float4*)(Xp + (size_t)(kn + xrk[q]) * NS + n0 + xc4[q] * 4);
        }

#pragma unroll
        for (int kk = 0; kk < 32; kk++) {
            float4 x0 = Xs[kk * 32 + tx * 2];
            float4 x1 = Xs[kk * 32 + tx * 2 + 1];
            float xr[8] = {x0.x, x0.y, x0.z, x0.w, x1.x, x1.y, x1.z, x1.w};
#pragma unroll
            for (int j = 0; j < 10; j++) {
                float w = Ws[(ty + 16 * j) * 33 + kk];
#pragma unroll
                for (int i = 0; i < 8; i++) acc[j][i] = fmaf(w, xr[i], acc[j][i]);
            }
        }
        __syncthreads();
    }

    int col = n0 + tx * 8;
#pragma unroll
    for (int j = 0; j < 10; j++) {
        int m = ty + 16 * j;
        float* dst;
        if (m < CC)            dst = g_feat + ((size_t)p * CC + m) * NS + col;
        else if (m < CC + HPG) dst = g_h + ((size_t)p * HPG + (m - CC)) * NS + col;
        else continue;
        float4 a = make_float4(acc[j][0], acc[j][1], acc[j][2], acc[j][3]);
        float4 b = make_float4(acc[j][4], acc[j][5], acc[j][6], acc[j][7]);
        *(float4*)dst = a;
        *(float4*)(dst + 4) = b;
    }
}

// ---------------------------------------------------------
// 4) BN1 stats: per (p,o) over 4096 cols
// ---------------------------------------------------------
__global__ void k_bn1() {
    int o = blockIdx.x, p = blockIdx.y;
    const float* hrow = g_h + ((size_t)p * HPG + o) * NS;
    float s = 0.f, s2 = 0.f;
    for (int e = threadIdx.x; e < NS; e += 256) {
        float v = hrow[e];
        s += v; s2 += v * v;
    }
#pragma unroll
    for (int off = 16; off; off >>= 1) {
        s  += __shfl_down_sync(0xffffffffu, s, off);
        s2 += __shfl_down_sync(0xffffffffu, s2, off);
    }
    __shared__ float rs[8], rs2[8];
    int lane = threadIdx.x & 31, w = threadIdx.x >> 5;
    if (lane == 0) { rs[w] = s; rs2[w] = s2; }
    __syncthreads();
    if (threadIdx.x == 0) {
        float ts = 0.f, ts2 = 0.f;
        for (int i = 0; i < 8; i++) { ts += rs[i]; ts2 += rs2[i]; }
        float mu = ts * (1.f / NS);
        float var = ts2 * (1.f / NS) - mu * mu;
        g_mu1[p * HPG + o] = mu;
        g_rs1[p * HPG + o] = rsqrtf(var + EPSV);
    }
}

// ---------------------------------------------------------
// 5) score + sum + argmax per (p,n); 64 threads (thread = s)
// ---------------------------------------------------------
__global__ void k_score(const float* __restrict__ w2,
                        const float* __restrict__ g1,
                        const float* __restrict__ b1) {
    int n = blockIdx.x, p = blockIdx.y;
    int t = threadIdx.x;
    __shared__ float sscale[HPG], sshift[HPG], sw2[HPG];
    if (t < HPG) {
        float mu = g_mu1[p * HPG + t], rsd = g_rs1[p * HPG + t];
        float ga = g1[p * HPG + t], be = b1[p * HPG + t];
        sscale[t] = rsd * ga;
        sshift[t] = be - mu * rsd * ga;
        sw2[t] = w2[p * HPG + t];
    }
    __syncthreads();
    const float* hb = g_h + (size_t)p * HPG * NS + n * 64 + t;
    float logit = 0.f;
#pragma unroll
    for (int o = 0; o < HPG; o++) {
        float v = hb[(size_t)o * NS];
        v = v * sscale[o] + sshift[o];
        v = (v >= 0.f) ? v : 0.01f * v;
        logit += v * sw2[o];
    }
    float sc = 1.f / (1.f + expf(-logit));
    g_score[((size_t)p * NN + n) * SS + t] = sc;
    __shared__ float svals[64];
    svals[t] = sc;
    __syncthreads();
    if (t < 32) {
        float v1 = svals[t], v2 = svals[t + 32];
        float sum = v1 + v2;
        float mv; int mi;
        if (v2 > v1) { mv = v2; mi = t + 32; } else { mv = v1; mi = t; }
#pragma unroll
        for (int off = 16; off; off >>= 1) {
            float ov = __shfl_down_sync(0xffffffffu, mv, off);
            int   oi = __shfl_down_sync(0xffffffffu, mi, off);
            float os = __shfl_down_sync(0xffffffffu, sum, off);
            sum += os;
            if (ov > mv || (ov == mv && oi < mi)) { mv = ov; mi = oi; }
        }
        if (t == 0) { g_ssum[p * NN + n] = sum; g_idx[p * NN + n] = mi; }
    }
}

// ---------------------------------------------------------
// 6) weighted pooling + selected frame gather; block (n,p), 256 threads
// ---------------------------------------------------------
__global__ void k_wpv(const float* __restrict__ tf, float* __restrict__ out) {
    int n = blockIdx.x, p = blockIdx.y;
    int t = threadIdx.x;
    int lane = t & 31, w = t >> 5;
    __shared__ float ssc[64];
    if (t < 64) ssc[t] = g_score[((size_t)p * NN + n) * SS + t];
    __syncthreads();
    float inv = 1.f / g_ssum[p * NN + n];
    const float* fb = g_feat + (size_t)p * CC * NS + n * 64;
    for (int j = 0; j < 16; j++) {
        int c = w * 16 + j;
        const float* fr = fb + (size_t)c * NS;
        float a = fr[lane] * ssc[lane] + fr[lane + 32] * ssc[lane + 32];
#pragma unroll
        for (int off = 16; off; off >>= 1) a += __shfl_down_sync(0xffffffffu, a, off);
        if (lane == 0) {
            float v = a * inv;
            g_wpv[((size_t)p * NN + n) * CC + c] = v;
            out[WPV_OFF + ((size_t)p * NN + n) * CC + c] = v;
        }
    }
    if (t < CC) {
        int idx = g_idx[p * NN + n];
        float v = tf[(size_t)n * (SS * CC * PP) + (size_t)idx * (CC * PP) + t * PP + p];
        out[SEL_OFF + ((size_t)p * NN + n) * CC + t] = v;
    }
}

// ---------------------------------------------------------
// 7) BN2: stats over n (64) per (p,c); fold gamma/beta into scale/shift
// ---------------------------------------------------------
__global__ void k_bn2(const float* __restrict__ g2, const float* __restrict__ b2) {
    int p = blockIdx.x;
    int c = threadIdx.x; // 128
    float s = 0.f, s2 = 0.f;
    for (int n = 0; n < NN; n++) {
        float v = g_wpv[((size_t)p * NN + n) * CC + c];
        s += v; s2 += v * v;
    }
    float m = s * (1.f / NN);
    float var = s2 * (1.f / NN) - m * m;
    float rsd = rsqrtf(var + EPSV);
    float ga = g2[p * CC + c], be = b2[p * CC + c];
    g_sc2[p * CC + c] = rsd * ga;
    g_sh2[p * CC + c] = be - m * rsd * ga;
}

// ---------------------------------------------------------
// 8) classifier GEMM: [2048 x 1000] = BN(wpv)[2048 x 128] * fc[128 x 1000]
// block tiles 64x64, 256 threads, TM=TN=4, K chunks of 64
// ---------------------------------------------------------
__global__ __launch_bounds__(256) void k_cls(const float* __restrict__ fc,
                                             float* __restrict__ out) {
    int kt = blockIdx.x * 64;
    int r0 = blockIdx.y * 64;
    __shared__ float As[64 * 64];
    __shared__ float Bs[64 * 64];
    int t = threadIdx.x, tx = t & 15, ty = t >> 4;
    float acc[4][4];
#pragma unroll
    for (int i = 0; i < 4; i++)
#pragma unroll
        for (int j = 0; j < 4; j++) acc[i][j] = 0.f;

    for (int kb = 0; kb < CC; kb += 64) {
        for (int f = t; f < 4096; f += 256) {
            int m = f >> 6, cc = f & 63;
            int row = r0 + m;
            int p = row >> 6;
            int ci = kb + cc;
            float v = g_wpv[(size_t)row * CC + ci];
            As[m * 64 + cc] = v * g_sc2[p * CC + ci] + g_sh2[p * CC + ci];
        }
        for (int f = t; f < 4096; f += 256) {
            int cc = f >> 6, kn = f & 63;
            int k = kt + kn;
            Bs[cc * 64 + kn] = (k < KK) ? fc[(size_t)(kb + cc) * KK + k] : 0.f;
        }
        __syncthreads();
#pragma unroll
        for (int kk = 0; kk < 64; kk++) {
            float a[4], b[4];
#pragma unroll
            for (int i = 0; i < 4; i++) a[i] = As[(ty * 4 + i) * 64 + kk];
#pragma unroll
            for (int j = 0; j < 4; j++) b[j] = Bs[kk * 64 + tx * 4 + j];
#pragma unroll
            for (int i = 0; i < 4; i++)
#pragma unroll
                for (int j = 0; j < 4; j++) acc[i][j] = fmaf(a[i], b[j], acc[i][j]);
        }
        __syncthreads();
    }
#pragma unroll
    for (int i = 0; i < 4; i++) {
        int row = r0 + ty * 4 + i;
#pragma unroll
        for (int j = 0; j < 4; j++) {
            int k = kt + tx * 4 + j;
            if (k < KK) out[PC_OFF + (size_t)row * KK + k] = acc[i][j];
        }
    }
}

// ---------------------------------------------------------
extern "C" void kernel_launch(void* const* d_in, const int* in_sizes, int n_in,
                              void* d_out, int out_size) {
    const float* tf = (const float*)d_in[0];
    const float* ts = (const float*)d_in[1];
    const float* tl = (const float*)d_in[2];
    const float* w1 = (const float*)d_in[3];
    const float* g1 = (const float*)d_in[4];
    const float* b1 = (const float*)d_in[5];
    const float* w2 = (const float*)d_in[6];
    const float* wd = (const float*)d_in[7];
    const float* g2 = (const float*)d_in[8];
    const float* b2 = (const float*)d_in[9];
    const float* fc = (const float*)d_in[10];
    float* out = (float*)d_out;

    k_transpose<<<dim3(NN, 3), 512>>>(tf, ts, tl);
    k_packw<<<PP, 256>>>(w1, wd);
    k_gemmA<<<dim3(NS / 128, PP), 256>>>();
    k_bn1<<<dim3(HPG, PP), 256>>>();
    k_score<<<dim3(NN, PP), 64>>>(w2, g1, b1);
    k_wpv<<<dim3(NN, PP), 256>>>(tf, out);
    k_bn2<<<PP, 128>>>(g2, b2);
    k_cls<<<dim3((KK + 63) / 64, PP), 256>>>(fc, out);
}

// round 5
// speedup vs baseline: 1.3490x; 1.3490x over previous
#include <cuda_runtime.h>
#include <cuda_bf16.h>
#include <cstdint>

#define NN 64
#define SS 64
#define CC 128
#define PP 32
#define KK 1000
#define HPG 24
#define CI 384               // 3*C
#define NS 4096              // N*S
#define EPSV 1e-5f

#define PC_OFF  0
#define WPV_OFF 2048000      // 32*64*1000
#define SEL_OFF 2310144      // + 32*64*128

// -------- device scratch (no allocations allowed) --------
__device__ __nv_bfloat16 g_xhi[(size_t)PP * NS * CI];   // [p][col][k] K-major
__device__ __nv_bfloat16 g_xlo[(size_t)PP * NS * CI];   // residual
__device__ float g_feat[(size_t)PP * CC * NS];   // [p][c][col]
__device__ float g_h[(size_t)PP * HPG * NS];     // [p][o][col]
__device__ float g_mu1[PP * HPG];
__device__ float g_rs1[PP * HPG];
__device__ float g_score[(size_t)PP * NN * SS];  // [p][n][s]
__device__ float g_ssum[PP * NN];
__device__ int   g_idx[PP * NN];
__device__ float g_wpv[(size_t)PP * NN * CC];    // [p][n][c]
__device__ float g_sc2[PP * CC];
__device__ float g_sh2[PP * CC];

// pack two floats -> bf16x2 (e0 in low half)
__device__ __forceinline__ uint32_t bpack(float e0, float e1) {
    uint32_t r;
    asm("cvt.rn.bf16x2.f32 %0, %1, %2;" : "=r"(r) : "f"(e1), "f"(e0));
    return r;
}
__device__ __forceinline__ void split8(float4 a, float4 b, uint4& hi, uint4& lo) {
    hi.x = bpack(a.x, a.y); hi.y = bpack(a.z, a.w);
    hi.z = bpack(b.x, b.y); hi.w = bpack(b.z, b.w);
    float r0 = __uint_as_float(hi.x << 16), r1 = __uint_as_float(hi.x & 0xffff0000u);
    float r2 = __uint_as_float(hi.y << 16), r3 = __uint_as_float(hi.y & 0xffff0000u);
    float r4 = __uint_as_float(hi.z << 16), r5 = __uint_as_float(hi.z & 0xffff0000u);
    float r6 = __uint_as_float(hi.w << 16), r7 = __uint_as_float(hi.w & 0xffff0000u);
    lo.x = bpack(a.x - r0, a.y - r1); lo.y = bpack(a.z - r2, a.w - r3);
    lo.z = bpack(b.x - r4, b.y - r5); lo.w = bpack(b.z - r6, b.w - r7);
}

__device__ __forceinline__ void mma_bf16(float* c, const uint32_t* a, const uint32_t* b) {
    asm volatile(
        "mma.sync.aligned.m16n8k16.row.col.f32.bf16.bf16.f32 "
        "{%0,%1,%2,%3},{%4,%5,%6,%7},{%8,%9},{%0,%1,%2,%3};"
        : "+f"(c[0]), "+f"(c[1]), "+f"(c[2]), "+f"(c[3])
        : "r"(a[0]), "r"(a[1]), "r"(a[2]), "r"(a[3]), "r"(b[0]), "r"(b[1]));
}

// ---------------------------------------------------------
// 1) transpose+split: t_*[n,s,c,p] -> g_xhi/g_xlo [p][n*64+s][tau*128+c]
// ---------------------------------------------------------
__global__ __launch_bounds__(512) void k_transpose(const float* __restrict__ tf,
                                                   const float* __restrict__ ts,
                                                   const float* __restrict__ tl) {
    int n = blockIdx.x, tau = blockIdx.y;
    const float* src = (tau == 0) ? tf : (tau == 1 ? ts : tl);
    __shared__ float tile[8][32][33];
    int t = threadIdx.x;
    const float* nbase = src + (size_t)n * (SS * CC * PP);
    for (int c0 = 0; c0 < CC; c0 += 32) {
        for (int s0 = 0; s0 < SS; s0 += 8) {
            for (int e = t; e < 8192; e += 512) {
                int si = e >> 10, r = e & 1023;
                int cl = r >> 5, pp = r & 31;
                tile[si][pp][cl] = nbase[(size_t)(s0 + si) * (CC * PP) + (size_t)(c0 + cl) * PP + pp];
            }
            __syncthreads();
            for (int e = t; e < 8192; e += 512) {
                int pp = e >> 8, r = e & 255;
                int si = r >> 5, cl = r & 31;
                float v = tile[si][pp][cl];
                __nv_bfloat16 h = __float2bfloat16(v);
                __nv_bfloat16 l = __float2bfloat16(v - __bfloat162float(h));
                size_t di = ((size_t)pp * NS + (size_t)(n * 64 + s0 + si)) * CI + tau * CC + c0 + cl;
                g_xhi[di] = h;
                g_xlo[di] = l;
            }
            __syncthreads();
        }
    }
}

// ---------------------------------------------------------
// 2) GEMM-A via mma.sync bf16 split (hh+hl+lh):
//    per (p, ntile): D[160x128] = W[160x384] * X[384x128]
//    8 warps: 2(M: 80 rows) x 4(N: 32 cols); warp = 5x4 m16n8 tiles
//    BK=32, smem k-stride 40 bf16 (conflict-free fragments)
// ---------------------------------------------------------
#define AST 40
__global__ __launch_bounds__(256) void k_gemmA(const float* __restrict__ wd,
                                               const float* __restrict__ w1) {
    __shared__ __nv_bfloat16 sAhi[160 * AST];
    __shared__ __nv_bfloat16 sAlo[160 * AST];
    __shared__ __nv_bfloat16 sBhi[128 * AST];
    __shared__ __nv_bfloat16 sBlo[128 * AST];

    int t = threadIdx.x, wid = t >> 5, lane = t & 31;
    int p = blockIdx.y, n0 = blockIdx.x * 128;
    int wm = wid >> 2, wn = wid & 3;        // warp M(0..1), N(0..3)
    int grp = lane >> 2, qid = lane & 3;

    float acc[5][4][4];
#pragma unroll
    for (int i = 0; i < 5; i++)
#pragma unroll
        for (int j = 0; j < 4; j++)
#pragma unroll
            for (int q = 0; q < 4; q++) acc[i][j][q] = 0.f;

    for (int kc = 0; kc < 12; kc++) {
        int k0 = kc * 32;
        // B: 128 rows x 32 k (hi+lo), 4 x uint4 per row
        for (int f = t; f < 512; f += 256) {
            int row = f >> 2, seg = f & 3;
            size_t gi = ((size_t)p * NS + (size_t)(n0 + row)) * CI + k0 + seg * 8;
            int so = row * AST + seg * 8;
            *(uint4*)(sBhi + so) = *(const uint4*)(g_xhi + gi);
            *(uint4*)(sBlo + so) = *(const uint4*)(g_xlo + gi);
        }
        // A: 160 rows x 32 k, split fp32 -> bf16 hi/lo
        for (int f = t; f < 640; f += 256) {
            int row = f >> 2, seg = f & 3;
            float4 a = make_float4(0.f, 0.f, 0.f, 0.f), b = a;
            if (row < CC) {
                const float* s = wd + ((size_t)p * CC + row) * CI + k0 + seg * 8;
                a = *(const float4*)s; b = *(const float4*)(s + 4);
            } else if (row < CC + HPG) {
                const float* s = w1 + ((size_t)p * HPG + (row - CC)) * CI + k0 + seg * 8;
                a = *(const float4*)s; b = *(const float4*)(s + 4);
            }
            uint4 hi, lo;
            split8(a, b, hi, lo);
            int so = row * AST + seg * 8;
            *(uint4*)(sAhi + so) = hi;
            *(uint4*)(sAlo + so) = lo;
        }
        __syncthreads();

#pragma unroll
        for (int ks = 0; ks < 2; ks++) {
            int kb = ks * 16 + qid * 2;    // element offset within chunk
            // A hi fragments (5 m-tiles)
            uint32_t Ah[5][4];
#pragma unroll
            for (int mt = 0; mt < 5; mt++) {
                int r = wm * 80 + mt * 16 + grp;
                const __nv_bfloat16* base = sAhi + r * AST + kb;
                Ah[mt][0] = *(const uint32_t*)(base);
                Ah[mt][1] = *(const uint32_t*)(base + 8 * AST);
                Ah[mt][2] = *(const uint32_t*)(base + 8);
                Ah[mt][3] = *(const uint32_t*)(base + 8 * AST + 8);
            }
            // B hi + lo fragments (4 n-tiles)
            uint32_t Bh[4][2], Bl[4][2];
#pragma unroll
            for (int nt = 0; nt < 4; nt++) {
                int nr = wn * 32 + nt * 8 + grp;
                const __nv_bfloat16* bh = sBhi + nr * AST + kb;
                const __nv_bfloat16* bl = sBlo + nr * AST + kb;
                Bh[nt][0] = *(const uint32_t*)(bh);
                Bh[nt][1] = *(const uint32_t*)(bh + 8);
                Bl[nt][0] = *(const uint32_t*)(bl);
                Bl[nt][1] = *(const uint32_t*)(bl + 8);
            }
            // hh + hl
#pragma unroll
            for (int mt = 0; mt < 5; mt++)
#pragma unroll
                for (int nt = 0; nt < 4; nt++) {
                    mma_bf16(acc[mt][nt], Ah[mt], Bh[nt]);
                    mma_bf16(acc[mt][nt], Ah[mt], Bl[nt]);
                }
            // lh: A lo
#pragma unroll
            for (int mt = 0; mt < 5; mt++) {
                int r = wm * 80 + mt * 16 + grp;
                const __nv_bfloat16* base = sAlo + r * AST + kb;
                uint32_t Al[4];
                Al[0] = *(const uint32_t*)(base);
                Al[1] = *(const uint32_t*)(base + 8 * AST);
                Al[2] = *(const uint32_t*)(base + 8);
                Al[3] = *(const uint32_t*)(base + 8 * AST + 8);
#pragma unroll
                for (int nt = 0; nt < 4; nt++)
                    mma_bf16(acc[mt][nt], Al, Bh[nt]);
            }
        }
        __syncthreads();
    }

    // epilogue: c0,c1 -> (row, col..col+1); c2,c3 -> (row+8, ..)
#pragma unroll
    for (int mt = 0; mt < 5; mt++) {
        int r = wm * 80 + mt * 16 + grp;
#pragma unroll
        for (int half = 0; half < 2; half++) {
            int m = r + half * 8;
            float* dst;
            if (m < CC)             dst = g_feat + ((size_t)p * CC + m) * NS;
            else if (m < CC + HPG)  dst = g_h + ((size_t)p * HPG + (m - CC)) * NS;
            else continue;
#pragma unroll
            for (int nt = 0; nt < 4; nt++) {
                int col = n0 + wn * 32 + nt * 8 + qid * 2;
                float2 v = make_float2(acc[mt][nt][half * 2], acc[mt][nt][half * 2 + 1]);
                *(float2*)(dst + col) = v;
            }
        }
    }
}

// ---------------------------------------------------------
// 4) BN1 stats: per (p,o) over 4096 cols
// ---------------------------------------------------------
__global__ void k_bn1() {
    int o = blockIdx.x, p = blockIdx.y;
    const float* hrow = g_h + ((size_t)p * HPG + o) * NS;
    float s = 0.f, s2 = 0.f;
    for (int e = threadIdx.x; e < NS; e += 256) {
        float v = hrow[e];
        s += v; s2 += v * v;
    }
#pragma unroll
    for (int off = 16; off; off >>= 1) {
        s  += __shfl_down_sync(0xffffffffu, s, off);
        s2 += __shfl_down_sync(0xffffffffu, s2, off);
    }
    __shared__ float rs[8], rs2[8];
    int lane = threadIdx.x & 31, w = threadIdx.x >> 5;
    if (lane == 0) { rs[w] = s; rs2[w] = s2; }
    __syncthreads();
    if (threadIdx.x == 0) {
        float ts = 0.f, ts2 = 0.f;
        for (int i = 0; i < 8; i++) { ts += rs[i]; ts2 += rs2[i]; }
        float mu = ts * (1.f / NS);
        float var = ts2 * (1.f / NS) - mu * mu;
        g_mu1[p * HPG + o] = mu;
        g_rs1[p * HPG + o] = rsqrtf(var + EPSV);
    }
}

// ---------------------------------------------------------
// 5) score + sum + argmax per (p,n); 64 threads (thread = s)
// ---------------------------------------------------------
__global__ void k_score(const float* __restrict__ w2,
                        const float* __restrict__ g1,
                        const float* __restrict__ b1) {
    int n = blockIdx.x, p = blockIdx.y;
    int t = threadIdx.x;
    __shared__ float sscale[HPG], sshift[HPG], sw2[HPG];
    if (t < HPG) {
        float mu = g_mu1[p * HPG + t], rsd = g_rs1[p * HPG + t];
        float ga = g1[p * HPG + t], be = b1[p * HPG + t];
        sscale[t] = rsd * ga;
        sshift[t] = be - mu * rsd * ga;
        sw2[t] = w2[p * HPG + t];
    }
    __syncthreads();
    const float* hb = g_h + (size_t)p * HPG * NS + n * 64 + t;
    float logit = 0.f;
#pragma unroll
    for (int o = 0; o < HPG; o++) {
        float v = hb[(size_t)o * NS];
        v = v * sscale[o] + sshift[o];
        v = (v >= 0.f) ? v : 0.01f * v;
        logit += v * sw2[o];
    }
    float sc = 1.f / (1.f + expf(-logit));
    g_score[((size_t)p * NN + n) * SS + t] = sc;
    __shared__ float svals[64];
    svals[t] = sc;
    __syncthreads();
    if (t < 32) {
        float v1 = svals[t], v2 = svals[t + 32];
        float sum = v1 + v2;
        float mv; int mi;
        if (v2 > v1) { mv = v2; mi = t + 32; } else { mv = v1; mi = t; }
#pragma unroll
        for (int off = 16; off; off >>= 1) {
            float ov = __shfl_down_sync(0xffffffffu, mv, off);
            int   oi = __shfl_down_sync(0xffffffffu, mi, off);
            float os = __shfl_down_sync(0xffffffffu, sum, off);
            sum += os;
            if (ov > mv || (ov == mv && oi < mi)) { mv = ov; mi = oi; }
        }
        if (t == 0) { g_ssum[p * NN + n] = sum; g_idx[p * NN + n] = mi; }
    }
}

// ---------------------------------------------------------
// 6) weighted pooling + selected frame gather; block (n,p), 256 threads
// ---------------------------------------------------------
__global__ void k_wpv(const float* __restrict__ tf, float* __restrict__ out) {
    int n = blockIdx.x, p = blockIdx.y;
    int t = threadIdx.x;
    int lane = t & 31, w = t >> 5;
    __shared__ float ssc[64];
    if (t < 64) ssc[t] = g_score[((size_t)p * NN + n) * SS + t];
    __syncthreads();
    float inv = 1.f / g_ssum[p * NN + n];
    const float* fb = g_feat + (size_t)p * CC * NS + n * 64;
    for (int j = 0; j < 16; j++) {
        int c = w * 16 + j;
        const float* fr = fb + (size_t)c * NS;
        float a = fr[lane] * ssc[lane] + fr[lane + 32] * ssc[lane + 32];
#pragma unroll
        for (int off = 16; off; off >>= 1) a += __shfl_down_sync(0xffffffffu, a, off);
        if (lane == 0) {
            float v = a * inv;
            g_wpv[((size_t)p * NN + n) * CC + c] = v;
            out[WPV_OFF + ((size_t)p * NN + n) * CC + c] = v;
        }
    }
    if (t < CC) {
        int idx = g_idx[p * NN + n];
        float v = tf[(size_t)n * (SS * CC * PP) + (size_t)idx * (CC * PP) + t * PP + p];
        out[SEL_OFF + ((size_t)p * NN + n) * CC + t] = v;
    }
}

// ---------------------------------------------------------
// 7) BN2: stats over n per (p,c)
// ---------------------------------------------------------
__global__ void k_bn2(const float* __restrict__ g2, const float* __restrict__ b2) {
    int p = blockIdx.x;
    int c = threadIdx.x; // 128
    float s = 0.f, s2 = 0.f;
    for (int n = 0; n < NN; n++) {
        float v = g_wpv[((size_t)p * NN + n) * CC + c];
        s += v; s2 += v * v;
    }
    float m = s * (1.f / NN);
    float var = s2 * (1.f / NN) - m * m;
    float rsd = rsqrtf(var + EPSV);
    float ga = g2[p * CC + c], be = b2[p * CC + c];
    g_sc2[p * CC + c] = rsd * ga;
    g_sh2[p * CC + c] = be - m * rsd * ga;
}

// ---------------------------------------------------------
// 8) classifier GEMM: [2048 x 1000] = BN(wpv)[2048 x 128] * fc[128 x 1000]
// ---------------------------------------------------------
__global__ __launch_bounds__(256) void k_cls(const float* __restrict__ fc,
                                             float* __restrict__ out) {
    int kt = blockIdx.x * 64;
    int r0 = blockIdx.y * 64;
    __shared__ float As[64 * 64];
    __shared__ float Bs[64 * 64];
    int t = threadIdx.x, tx = t & 15, ty = t >> 4;
    float acc[4][4];
#pragma unroll
    for (int i = 0; i < 4; i++)
#pragma unroll
        for (int j = 0; j < 4; j++) acc[i][j] = 0.f;

    for (int kb = 0; kb < CC; kb += 64) {
        for (int f = t; f < 4096; f += 256) {
            int m = f >> 6, cc = f & 63;
            int row = r0 + m;
            int p = row >> 6;
            int ci = kb + cc;
            float v = g_wpv[(size_t)row * CC + ci];
            As[m * 64 + cc] = v * g_sc2[p * CC + ci] + g_sh2[p * CC + ci];
        }
        for (int f = t; f < 4096; f += 256) {
            int cc = f >> 6, kn = f & 63;
            int k = kt + kn;
            Bs[cc * 64 + kn] = (k < KK) ? fc[(size_t)(kb + cc) * KK + k] : 0.f;
        }
        __syncthreads();
#pragma unroll
        for (int kk = 0; kk < 64; kk++) {
            float a[4], b[4];
#pragma unroll
            for (int i = 0; i < 4; i++) a[i] = As[(ty * 4 + i) * 64 + kk];
#pragma unroll
            for (int j = 0; j < 4; j++) b[j] = Bs[kk * 64 + tx * 4 + j];
#pragma unroll
            for (int i = 0; i < 4; i++)
#pragma unroll
                for (int j = 0; j < 4; j++) acc[i][j] = fmaf(a[i], b[j], acc[i][j]);
        }
        __syncthreads();
    }
#pragma unroll
    for (int i = 0; i < 4; i++) {
        int row = r0 + ty * 4 + i;
#pragma unroll
        for (int j = 0; j < 4; j++) {
            int k = kt + tx * 4 + j;
            if (k < KK) out[PC_OFF + (size_t)row * KK + k] = acc[i][j];
        }
    }
}

// ---------------------------------------------------------
extern "C" void kernel_launch(void* const* d_in, const int* in_sizes, int n_in,
                              void* d_out, int out_size) {
    const float* tf = (const float*)d_in[0];
    const float* ts = (const float*)d_in[1];
    const float* tl = (const float*)d_in[2];
    const float* w1 = (const float*)d_in[3];
    const float* g1 = (const float*)d_in[4];
    const float* b1 = (const float*)d_in[5];
    const float* w2 = (const float*)d_in[6];
    const float* wd = (const float*)d_in[7];
    const float* g2 = (const float*)d_in[8];
    const float* b2 = (const float*)d_in[9];
    const float* fc = (const float*)d_in[10];
    float* out = (float*)d_out;

    k_transpose<<<dim3(NN, 3), 512>>>(tf, ts, tl);
    k_gemmA<<<dim3(NS / 128, PP), 256>>>(wd, w1);
    k_bn1<<<dim3(HPG, PP), 256>>>();
    k_score<<<dim3(NN, PP), 64>>>(w2, g1, b1);
    k_wpv<<<dim3(NN, PP), 256>>>(tf, out);
    k_bn2<<<PP, 128>>>(g2, b2);
    k_cls<<<dim3((KK + 63) / 64, PP), 256>>>(fc, out);
}

// round 13
// speedup vs baseline: 2.0773x; 1.5399x over previous
#include <cuda_runtime.h>
#include <cuda_bf16.h>
#include <cstdint>

#define NN 64
#define SS 64
#define CC 128
#define PP 32
#define KK 1000
#define HPG 24
#define CI 384               // 3*C
#define NS 4096              // N*S
#define EPSV 1e-5f

#define PC_OFF  0
#define WPV_OFF 2048000      // 32*64*1000
#define SEL_OFF 2310144      // + 32*64*128

// -------- device scratch (no allocations allowed) --------
__device__ __nv_bfloat16 g_xhi[(size_t)PP * NS * CI];   // [p][col][k] K-major
__device__ __nv_bfloat16 g_xlo[(size_t)PP * NS * CI];   // residual
__device__ __nv_bfloat16 g_whi[(size_t)PP * 160 * CI];  // packed W split hi
__device__ __nv_bfloat16 g_wlo[(size_t)PP * 160 * CI];  // packed W split lo
__device__ float g_feat[(size_t)PP * CC * NS];   // [p][c][col]
__device__ float g_h[(size_t)PP * HPG * NS];     // [p][o][col]
__device__ float g_mu1[PP * HPG];
__device__ float g_rs1[PP * HPG];
__device__ float g_score[(size_t)PP * NN * SS];  // [p][n][s]
__device__ float g_ssum[PP * NN];
__device__ int   g_idx[PP * NN];
__device__ float g_wpv[(size_t)PP * NN * CC];    // [p][n][c]
__device__ float g_sc2[PP * CC];
__device__ float g_sh2[PP * CC];

// pack two floats -> bf16x2 (e0 in low half)
__device__ __forceinline__ uint32_t bpack(float e0, float e1) {
    uint32_t r;
    asm("cvt.rn.bf16x2.f32 %0, %1, %2;" : "=r"(r) : "f"(e1), "f"(e0));
    return r;
}
__device__ __forceinline__ void split8(float4 a, float4 b, uint4& hi, uint4& lo) {
    hi.x = bpack(a.x, a.y); hi.y = bpack(a.z, a.w);
    hi.z = bpack(b.x, b.y); hi.w = bpack(b.z, b.w);
    float r0 = __uint_as_float(hi.x << 16), r1 = __uint_as_float(hi.x & 0xffff0000u);
    float r2 = __uint_as_float(hi.y << 16), r3 = __uint_as_float(hi.y & 0xffff0000u);
    float r4 = __uint_as_float(hi.z << 16), r5 = __uint_as_float(hi.z & 0xffff0000u);
    float r6 = __uint_as_float(hi.w << 16), r7 = __uint_as_float(hi.w & 0xffff0000u);
    lo.x = bpack(a.x - r0, a.y - r1); lo.y = bpack(a.z - r2, a.w - r3);
    lo.z = bpack(b.x - r4, b.y - r5); lo.w = bpack(b.z - r6, b.w - r7);
}

__device__ __forceinline__ void mma_bf16(float* c, const uint32_t* a, const uint32_t* b) {
    asm volatile(
        "mma.sync.aligned.m16n8k16.row.col.f32.bf16.bf16.f32 "
        "{%0,%1,%2,%3},{%4,%5,%6,%7},{%8,%9},{%0,%1,%2,%3};"
        : "+f"(c[0]), "+f"(c[1]), "+f"(c[2]), "+f"(c[3])
        : "r"(a[0]), "r"(a[1]), "r"(a[2]), "r"(a[3]), "r"(b[0]), "r"(b[1]));
}

__device__ __forceinline__ uint32_t smem_u32(const void* p) {
    uint32_t a;
    asm("{ .reg .u64 t; cvta.to.shared.u64 t, %1; cvt.u32.u64 %0, t; }" : "=r"(a) : "l"(p));
    return a;
}
#define CP16(dst, src) \
    asm volatile("cp.async.cg.shared.global [%0], [%1], 16;" :: "r"(dst), "l"(src))
#define CP_COMMIT() asm volatile("cp.async.commit_group;" ::: "memory")
#define CP_WAIT1()  asm volatile("cp.async.wait_group 1;" ::: "memory")
#define CP_WAIT0()  asm volatile("cp.async.wait_group 0;" ::: "memory")

// ---------------------------------------------------------
// 1) transpose+split: t_*[n,s,c,p] -> g_xhi/g_xlo [p][n*64+s][tau*128+c]
// ---------------------------------------------------------
__global__ __launch_bounds__(512) void k_transpose(const float* __restrict__ tf,
                                                   const float* __restrict__ ts,
                                                   const float* __restrict__ tl) {
    int n = blockIdx.x, tau = blockIdx.y;
    const float* src = (tau == 0) ? tf : (tau == 1 ? ts : tl);
    __shared__ float tile[8][32][33];
    int t = threadIdx.x;
    const float* nbase = src + (size_t)n * (SS * CC * PP);
    for (int c0 = 0; c0 < CC; c0 += 32) {
        for (int s0 = 0; s0 < SS; s0 += 8) {
            for (int e = t; e < 8192; e += 512) {
                int si = e >> 10, r = e & 1023;
                int cl = r >> 5, pp = r & 31;
                tile[si][pp][cl] = nbase[(size_t)(s0 + si) * (CC * PP) + (size_t)(c0 + cl) * PP + pp];
            }
            __syncthreads();
            // packed 4B stores: 2 consecutive k per thread
            for (int e = t; e < 4096; e += 512) {
                int pp = e >> 7, r = e & 127;
                int si = r >> 4, cl = (r & 15) * 2;
                float v0 = tile[si][pp][cl], v1 = tile[si][pp][cl + 1];
                uint32_t hi = bpack(v0, v1);
                float r0 = __uint_as_float(hi << 16), r1 = __uint_as_float(hi & 0xffff0000u);
                uint32_t lo = bpack(v0 - r0, v1 - r1);
                size_t di = ((size_t)pp * NS + (size_t)(n * 64 + s0 + si)) * CI + tau * CC + c0 + cl;
                *(uint32_t*)(g_xhi + di) = hi;
                *(uint32_t*)(g_xlo + di) = lo;
            }
            __syncthreads();
        }
    }
}

// ---------------------------------------------------------
// 1b) W split precompute: rows 0..127 wd, 128..151 w1, 152..159 zero
// ---------------------------------------------------------
__global__ void k_wsplit(const float* __restrict__ wd, const float* __restrict__ w1) {
    int p = blockIdx.x;
    for (int f = threadIdx.x; f < 160 * 48; f += 256) {
        int row = f / 48, seg = f % 48;
        float4 a = make_float4(0.f, 0.f, 0.f, 0.f), b = a;
        if (row < CC) {
            const float* s = wd + ((size_t)p * CC + row) * CI + seg * 8;
            a = *(const float4*)s; b = *(const float4*)(s + 4);
        } else if (row < CC + HPG) {
            const float* s = w1 + ((size_t)p * HPG + (row - CC)) * CI + seg * 8;
            a = *(const float4*)s; b = *(const float4*)(s + 4);
        }
        uint4 hi, lo;
        split8(a, b, hi, lo);
        size_t o = ((size_t)p * 160 + row) * CI + seg * 8;
        *(uint4*)(g_whi + o) = hi;
        *(uint4*)(g_wlo + o) = lo;
    }
}

// ---------------------------------------------------------
// 2) GEMM-A, cp.async 2-stage pipeline, bf16 split (hh+hl+lh)
//    per (p, ntile): D[160x128] = W[160x384] * X[384x128]
//    8 warps 2(M)x4(N); warp = 5x4 m16n8k16 tiles; BK=32, k-stride 40
// ---------------------------------------------------------
#define AST 40
#define OFF_AHI 0
#define OFF_ALO (160 * AST)
#define OFF_BHI (320 * AST)
#define OFF_BLO (448 * AST)
#define STG_ELEMS (576 * AST)          // 23040 bf16 = 46080 B
#define GEMM_SMEM (2 * STG_ELEMS * 2)  // 92160 B

__global__ __launch_bounds__(256, 2) void k_gemmA() {
    extern __shared__ __nv_bfloat16 sm[];
    int t = threadIdx.x, wid = t >> 5, lane = t & 31;
    int p = blockIdx.y, n0 = blockIdx.x * 128;
    int wm = wid >> 2, wn = wid & 3;
    int grp = lane >> 2, qid = lane & 3;
    uint32_t smb = smem_u32(sm);

    float acc[5][4][4];
#pragma unroll
    for (int i = 0; i < 5; i++)
#pragma unroll
        for (int j = 0; j < 4; j++)
#pragma unroll
            for (int q = 0; q < 4; q++) acc[i][j][q] = 0.f;

    const __nv_bfloat16* whiP = g_whi + (size_t)p * 160 * CI;
    const __nv_bfloat16* wloP = g_wlo + (size_t)p * 160 * CI;
    const __nv_bfloat16* xhiP = g_xhi + ((size_t)p * NS + n0) * CI;
    const __nv_bfloat16* xloP = g_xlo + ((size_t)p * NS + n0) * CI;

    // issue one stage of cp.asyncs (2304 16B ops, 9 per thread)
    auto issue = [&](int kc, int buf) {
        int k0 = kc * 32;
        uint32_t base = smb + buf * (STG_ELEMS * 2);
#pragma unroll
        for (int i = 0; i < 9; i++) {
            int f = t + i * 256;
            if (f < 640) {
                int row = f >> 2, seg = f & 3;
                CP16(base + (OFF_AHI + row * AST + seg * 8) * 2,
                     whiP + (size_t)row * CI + k0 + seg * 8);
            } else if (f < 1280) {
                int g = f - 640, row = g >> 2, seg = g & 3;
                CP16(base + (OFF_ALO + row * AST + seg * 8) * 2,
                     wloP + (size_t)row * CI + k0 + seg * 8);
            } else if (f < 1792) {
                int g = f - 1280, row = g >> 2, seg = g & 3;
                CP16(base + (OFF_BHI + row * AST + seg * 8) * 2,
                     xhiP + (size_t)row * CI + k0 + seg * 8);
            } else {
                int g = f - 1792, row = g >> 2, seg = g & 3;
                CP16(base + (OFF_BLO + row * AST + seg * 8) * 2,
                     xloP + (size_t)row * CI + k0 + seg * 8);
            }
        }
    };

    issue(0, 0);
    CP_COMMIT();

    for (int kc = 0; kc < 12; kc++) {
        if (kc + 1 < 12) {
            issue(kc + 1, (kc + 1) & 1);
            CP_COMMIT();
            CP_WAIT1();
        } else {
            CP_WAIT0();
        }
        __syncthreads();

        const __nv_bfloat16* S = sm + (kc & 1) * STG_ELEMS;
#pragma unroll
        for (int ks = 0; ks < 2; ks++) {
            int kb = ks * 16 + qid * 2;
            uint32_t Bh[4][2], Bl[4][2];
#pragma unroll
            for (int nt = 0; nt < 4; nt++) {
                int nr = wn * 32 + nt * 8 + grp;
                const __nv_bfloat16* bh = S + OFF_BHI + nr * AST + kb;
                const __nv_bfloat16* bl = S + OFF_BLO + nr * AST + kb;
                Bh[nt][0] = *(const uint32_t*)(bh);
                Bh[nt][1] = *(const uint32_t*)(bh + 8);
                Bl[nt][0] = *(const uint32_t*)(bl);
                Bl[nt][1] = *(const uint32_t*)(bl + 8);
            }
#pragma unroll
            for (int mt = 0; mt < 5; mt++) {
                int r = wm * 80 + mt * 16 + grp;
                const __nv_bfloat16* a = S + OFF_AHI + r * AST + kb;
                uint32_t Af[4];
                Af[0] = *(const uint32_t*)(a);
                Af[1] = *(const uint32_t*)(a + 8 * AST);
                Af[2] = *(const uint32_t*)(a + 8);
                Af[3] = *(const uint32_t*)(a + 8 * AST + 8);
#pragma unroll
                for (int nt = 0; nt < 4; nt++) mma_bf16(acc[mt][nt], Af, Bh[nt]);
#pragma unroll
                for (int nt = 0; nt < 4; nt++) mma_bf16(acc[mt][nt], Af, Bl[nt]);
                const __nv_bfloat16* al = S + OFF_ALO + r * AST + kb;
                Af[0] = *(const uint32_t*)(al);
                Af[1] = *(const uint32_t*)(al + 8 * AST);
                Af[2] = *(const uint32_t*)(al + 8);
                Af[3] = *(const uint32_t*)(al + 8 * AST + 8);
#pragma unroll
                for (int nt = 0; nt < 4; nt++) mma_bf16(acc[mt][nt], Af, Bh[nt]);
            }
        }
        __syncthreads();
    }

    // epilogue
#pragma unroll
    for (int mt = 0; mt < 5; mt++) {
        int r = wm * 80 + mt * 16 + grp;
#pragma unroll
        for (int half = 0; half < 2; half++) {
            int m = r + half * 8;
            float* dst;
            if (m < CC)             dst = g_feat + ((size_t)p * CC + m) * NS;
            else if (m < CC + HPG)  dst = g_h + ((size_t)p * HPG + (m - CC)) * NS;
            else continue;
#pragma unroll
            for (int nt = 0; nt < 4; nt++) {
                int col = n0 + wn * 32 + nt * 8 + qid * 2;
                *(float2*)(dst + col) =
                    make_float2(acc[mt][nt][half * 2], acc[mt][nt][half * 2 + 1]);
            }
        }
    }
}

// ---------------------------------------------------------
// 4) BN1 stats: per (p,o) over 4096 cols
// ---------------------------------------------------------
__global__ void k_bn1() {
    int o = blockIdx.x, p = blockIdx.y;
    const float* hrow = g_h + ((size_t)p * HPG + o) * NS;
    float s = 0.f, s2 = 0.f;
    for (int e = threadIdx.x; e < NS; e += 256) {
        float v = hrow[e];
        s += v; s2 += v * v;
    }
#pragma unroll
    for (int off = 16; off; off >>= 1) {
        s  += __shfl_down_sync(0xffffffffu, s, off);
        s2 += __shfl_down_sync(0xffffffffu, s2, off);
    }
    __shared__ float rs[8], rs2[8];
    int lane = threadIdx.x & 31, w = threadIdx.x >> 5;
    if (lane == 0) { rs[w] = s; rs2[w] = s2; }
    __syncthreads();
    if (threadIdx.x == 0) {
        float ts = 0.f, ts2 = 0.f;
        for (int i = 0; i < 8; i++) { ts += rs[i]; ts2 += rs2[i]; }
        float mu = ts * (1.f / NS);
        float var = ts2 * (1.f / NS) - mu * mu;
        g_mu1[p * HPG + o] = mu;
        g_rs1[p * HPG + o] = rsqrtf(var + EPSV);
    }
}

// ---------------------------------------------------------
// 5) score + sum + argmax per (p,n); 64 threads (thread = s)
// ---------------------------------------------------------
__global__ void k_score(const float* __restrict__ w2,
                        const float* __restrict__ g1,
                        const float* __restrict__ b1) {
    int n = blockIdx.x, p = blockIdx.y;
    int t = threadIdx.x;
    __shared__ float sscale[HPG], sshift[HPG], sw2[HPG];
    if (t < HPG) {
        float mu = g_mu1[p * HPG + t], rsd = g_rs1[p * HPG + t];
        float ga = g1[p * HPG + t], be = b1[p * HPG + t];
        sscale[t] = rsd * ga;
        sshift[t] = be - mu * rsd * ga;
        sw2[t] = w2[p * HPG + t];
    }
    __syncthreads();
    const float* hb = g_h + (size_t)p * HPG * NS + n * 64 + t;
    float logit = 0.f;
#pragma unroll
    for (int o = 0; o < HPG; o++) {
        float v = hb[(size_t)o * NS];
        v = v * sscale[o] + sshift[o];
        v = (v >= 0.f) ? v : 0.01f * v;
        logit += v * sw2[o];
    }
    float sc = 1.f / (1.f + expf(-logit));
    g_score[((size_t)p * NN + n) * SS + t] = sc;
    __shared__ float svals[64];
    svals[t] = sc;
    __syncthreads();
    if (t < 32) {
        float v1 = svals[t], v2 = svals[t + 32];
        float sum = v1 + v2;
        float mv; int mi;
        if (v2 > v1) { mv = v2; mi = t + 32; } else { mv = v1; mi = t; }
#pragma unroll
        for (int off = 16; off; off >>= 1) {
            float ov = __shfl_down_sync(0xffffffffu, mv, off);
            int   oi = __shfl_down_sync(0xffffffffu, mi, off);
            float os = __shfl_down_sync(0xffffffffu, sum, off);
            sum += os;
            if (ov > mv || (ov == mv && oi < mi)) { mv = ov; mi = oi; }
        }
        if (t == 0) { g_ssum[p * NN + n] = sum; g_idx[p * NN + n] = mi; }
    }
}

// ---------------------------------------------------------
// 6) weighted pooling + selected frame gather; block (n,p), 256 threads
// ---------------------------------------------------------
__global__ void k_wpv(const float* __restrict__ tf, float* __restrict__ out) {
    int n = blockIdx.x, p = blockIdx.y;
    int t = threadIdx.x;
    int lane = t & 31, w = t >> 5;
    __shared__ float ssc[64];
    if (t < 64) ssc[t] = g_score[((size_t)p * NN + n) * SS + t];
    __syncthreads();
    float inv = 1.f / g_ssum[p * NN + n];
    const float* fb = g_feat + (size_t)p * CC * NS + n * 64;
    for (int j = 0; j < 16; j++) {
        int c = w * 16 + j;
        const float* fr = fb + (size_t)c * NS;
        float a = fr[lane] * ssc[lane] + fr[lane + 32] * ssc[lane + 32];
#pragma unroll
        for (int off = 16; off; off >>= 1) a += __shfl_down_sync(0xffffffffu, a, off);
        if (lane == 0) {
            float v = a * inv;
            g_wpv[((size_t)p * NN + n) * CC + c] = v;
            out[WPV_OFF + ((size_t)p * NN + n) * CC + c] = v;
        }
    }
    if (t < CC) {
        int idx = g_idx[p * NN + n];
        float v = tf[(size_t)n * (SS * CC * PP) + (size_t)idx * (CC * PP) + t * PP + p];
        out[SEL_OFF + ((size_t)p * NN + n) * CC + t] = v;
    }
}

// ---------------------------------------------------------
// 7) BN2: stats over n per (p,c)
// ---------------------------------------------------------
__global__ void k_bn2(const float* __restrict__ g2, const float* __restrict__ b2) {
    int p = blockIdx.x;
    int c = threadIdx.x; // 128
    float s = 0.f, s2 = 0.f;
    for (int n = 0; n < NN; n++) {
        float v = g_wpv[((size_t)p * NN + n) * CC + c];
        s += v; s2 += v * v;
    }
    float m = s * (1.f / NN);
    float var = s2 * (1.f / NN) - m * m;
    float rsd = rsqrtf(var + EPSV);
    float ga = g2[p * CC + c], be = b2[p * CC + c];
    g_sc2[p * CC + c] = rsd * ga;
    g_sh2[p * CC + c] = be - m * rsd * ga;
}

// ---------------------------------------------------------
// 8) classifier GEMM: [2048 x 1000] = BN(wpv)[2048 x 128] * fc[128 x 1000]
// ---------------------------------------------------------
__global__ __launch_bounds__(256) void k_cls(const float* __restrict__ fc,
                                             float* __restrict__ out) {
    int kt = blockIdx.x * 64;
    int r0 = blockIdx.y * 64;
    __shared__ float As[64 * 64];
    __shared__ float Bs[64 * 64];
    int t = threadIdx.x, tx = t & 15, ty = t >> 4;
    float acc[4][4];
#pragma unroll
    for (int i = 0; i < 4; i++)
#pragma unroll
        for (int j = 0; j < 4; j++) acc[i][j] = 0.f;

    for (int kb = 0; kb < CC; kb += 64) {
        for (int f = t; f < 4096; f += 256) {
            int m = f >> 6, cc = f & 63;
            int row = r0 + m;
            int p = row >> 6;
            int ci = kb + cc;
            float v = g_wpv[(size_t)row * CC + ci];
            As[m * 64 + cc] = v * g_sc2[p * CC + ci] + g_sh2[p * CC + ci];
        }
        for (int f = t; f < 4096; f += 256) {
            int cc = f >> 6, kn = f & 63;
            int k = kt + kn;
            Bs[cc * 64 + kn] = (k < KK) ? fc[(size_t)(kb + cc) * KK + k] : 0.f;
        }
        __syncthreads();
#pragma unroll
        for (int kk = 0; kk < 64; kk++) {
            float a[4], b[4];
#pragma unroll
            for (int i = 0; i < 4; i++) a[i] = As[(ty * 4 + i) * 64 + kk];
#pragma unroll
            for (int j = 0; j < 4; j++) b[j] = Bs[kk * 64 + tx * 4 + j];
#pragma unroll
            for (int i = 0; i < 4; i++)
#pragma unroll
                for (int j = 0; j < 4; j++) acc[i][j] = fmaf(a[i], b[j], acc[i][j]);
        }
        __syncthreads();
    }
#pragma unroll
    for (int i = 0; i < 4; i++) {
        int row = r0 + ty * 4 + i;
#pragma unroll
        for (int j = 0; j < 4; j++) {
            int k = kt + tx * 4 + j;
            if (k < KK) out[PC_OFF + (size_t)row * KK + k] = acc[i][j];
        }
    }
}

// ---------------------------------------------------------
extern "C" void kernel_launch(void* const* d_in, const int* in_sizes, int n_in,
                              void* d_out, int out_size) {
    const float* tf = (const float*)d_in[0];
    const float* ts = (const float*)d_in[1];
    const float* tl = (const float*)d_in[2];
    const float* w1 = (const float*)d_in[3];
    const float* g1 = (const float*)d_in[4];
    const float* b1 = (const float*)d_in[5];
    const float* w2 = (const float*)d_in[6];
    const float* wd = (const float*)d_in[7];
    const float* g2 = (const float*)d_in[8];
    const float* b2 = (const float*)d_in[9];
    const float* fc = (const float*)d_in[10];
    float* out = (float*)d_out;

    cudaFuncSetAttribute(k_gemmA, cudaFuncAttributeMaxDynamicSharedMemorySize, GEMM_SMEM);

    k_transpose<<<dim3(NN, 3), 512>>>(tf, ts, tl);
    k_wsplit<<<PP, 256>>>(wd, w1);
    k_gemmA<<<dim3(NS / 128, PP), 256, GEMM_SMEM>>>();
    k_bn1<<<dim3(HPG, PP), 256>>>();
    k_score<<<dim3(NN, PP), 64>>>(w2, g1, b1);
    k_wpv<<<dim3(NN, PP), 256>>>(tf, out);
    k_bn2<<<PP, 128>>>(g2, b2);
    k_cls<<<dim3((KK + 63) / 64, PP), 256>>>(fc, out);
}